// round 1
// baseline (speedup 1.0000x reference)
#include <cuda_runtime.h>
#include <cuda_bf16.h>
#include <math.h>

// Problem constants
#define BB 4
#define TT 2048
#define CC 1024
#define HH 16
#define DD 64
#define EPS 1.1920929e-07f

// ---------------------------------------------------------------------------
// Scratch buffers (allocation-free rule: __device__ globals)
// ---------------------------------------------------------------------------
__device__ float g_q[BB * TT * CC];
__device__ float g_k[BB * TT * CC];
__device__ float g_v[BB * TT * CC];
__device__ float g_y[BB * TT * CC];

// ---------------------------------------------------------------------------
// GEMM: C[m,n] = sum_k A[m,k] * W[n,k]   (A row-major MxK, W row-major NxK)
// 64x64 tile, BK=16, 256 threads, 4x4 micro-tile per thread.
// ---------------------------------------------------------------------------
#define BM 64
#define BN 64
#define BK 16

__global__ __launch_bounds__(256) void gemm_nt(
    const float* __restrict__ A, const float* __restrict__ W,
    float* __restrict__ Cout, int M, int N, int K)
{
    __shared__ float As[BK][BM];
    __shared__ float Ws[BK][BN];

    const int tid = threadIdx.x;
    const int tx = tid & 15;        // 0..15
    const int ty = tid >> 4;        // 0..15
    const int m0 = blockIdx.y * BM;
    const int n0 = blockIdx.x * BN;

    const int lr = tid >> 2;        // 0..63 row within tile
    const int lc = (tid & 3) << 2;  // 0,4,8,12 (k offset, float4)

    float acc[4][4] = {};

    for (int k0 = 0; k0 < K; k0 += BK) {
        float4 av = *(const float4*)&A[(size_t)(m0 + lr) * K + k0 + lc];
        float4 wv = *(const float4*)&W[(size_t)(n0 + lr) * K + k0 + lc];
        As[lc + 0][lr] = av.x; As[lc + 1][lr] = av.y;
        As[lc + 2][lr] = av.z; As[lc + 3][lr] = av.w;
        Ws[lc + 0][lr] = wv.x; Ws[lc + 1][lr] = wv.y;
        Ws[lc + 2][lr] = wv.z; Ws[lc + 3][lr] = wv.w;
        __syncthreads();

        #pragma unroll
        for (int k = 0; k < BK; k++) {
            float a[4], b[4];
            #pragma unroll
            for (int i = 0; i < 4; i++) a[i] = As[k][ty * 4 + i];
            #pragma unroll
            for (int j = 0; j < 4; j++) b[j] = Ws[k][tx * 4 + j];
            #pragma unroll
            for (int i = 0; i < 4; i++)
                #pragma unroll
                for (int j = 0; j < 4; j++)
                    acc[i][j] = fmaf(a[i], b[j], acc[i][j]);
        }
        __syncthreads();
    }

    #pragma unroll
    for (int i = 0; i < 4; i++) {
        float4 o = make_float4(acc[i][0], acc[i][1], acc[i][2], acc[i][3]);
        *(float4*)&Cout[(size_t)(m0 + ty * 4 + i) * N + n0 + tx * 4] = o;
    }
}

// ---------------------------------------------------------------------------
// RoPE (concat-half variant) + RMSnorm over D=64, in-place on q and k.
// One warp per (b,t,h) row; blockIdx.y selects q vs k.
// ---------------------------------------------------------------------------
__global__ __launch_bounds__(32) void rope_rms(
    float* __restrict__ q, float* __restrict__ k,
    const float* __restrict__ cs, const float* __restrict__ sn)
{
    const int row = blockIdx.x;                 // (b*T + t)*H + h
    const int t = (row / HH) % TT;
    float* p = (blockIdx.y == 0 ? q : k) + (size_t)row * DD;

    const int i = threadIdx.x;                  // 0..31
    float x1 = p[i];
    float x2 = p[i + 32];
    float c = cs[t * 32 + i];
    float s = sn[t * 32 + i];
    float y1 = x1 * c + x2 * s;
    float y2 = -x1 * s + x2 * c;

    float ss = y1 * y1 + y2 * y2;
    #pragma unroll
    for (int o = 16; o; o >>= 1) ss += __shfl_xor_sync(0xffffffffu, ss, o);
    float r = rsqrtf(ss * (1.0f / 64.0f) + EPS);

    p[i]      = y1 * r;
    p[i + 32] = y2 * r;
}

// ---------------------------------------------------------------------------
// Flash attention: non-causal, fp32, 64 queries x 64 keys per step, D=64.
// grid = (T/64, B*H), 256 threads, online softmax.
// ---------------------------------------------------------------------------
#define QPAD 65  // padded row stride to dodge bank conflicts

__global__ __launch_bounds__(256) void flash_attn(
    const float* __restrict__ q, const float* __restrict__ kk,
    const float* __restrict__ vv, float* __restrict__ y)
{
    extern __shared__ float sm[];
    float* Qs   = sm;                   // 64 x 65
    float* Ks   = Qs + 64 * QPAD;       // 64 x 65
    float* Ss   = Ks + 64 * QPAD;       // 64 x 65
    float* Vs   = Ss + 64 * QPAD;       // 64 x 64
    float* mrow = Vs + 64 * 64;         // 64
    float* lrow = mrow + 64;            // 64
    float* arow = lrow + 64;            // 64

    const int tid = threadIdx.x;
    const int tx = tid & 15;
    const int ty = tid >> 4;

    const int bh = blockIdx.y;
    const int b = bh / HH;
    const int h = bh % HH;
    const int q0 = blockIdx.x * 64;

    const size_t base = (size_t)b * TT * CC + (size_t)h * DD;

    // Load Q tile
    for (int idx = tid; idx < 64 * 64; idx += 256) {
        int r = idx >> 6, d = idx & 63;
        Qs[r * QPAD + d] = q[base + (size_t)(q0 + r) * CC + d];
    }
    if (tid < 64) { mrow[tid] = -1e30f; lrow[tid] = 0.0f; }

    float acc[4][4] = {};
    const float scale = 0.125f;   // 1/sqrt(64)

    for (int j0 = 0; j0 < TT; j0 += 64) {
        // Load K, V tiles
        for (int idx = tid; idx < 64 * 64; idx += 256) {
            int r = idx >> 6, d = idx & 63;
            size_t g = base + (size_t)(j0 + r) * CC + d;
            Ks[r * QPAD + d] = kk[g];
            Vs[r * 64 + d]   = vv[g];
        }
        __syncthreads();

        // S = scale * Q K^T  (4x4 per thread)
        float sacc[4][4] = {};
        #pragma unroll 8
        for (int k = 0; k < 64; k++) {
            float a[4], bq[4];
            #pragma unroll
            for (int i = 0; i < 4; i++) a[i] = Qs[(ty * 4 + i) * QPAD + k];
            #pragma unroll
            for (int j = 0; j < 4; j++) bq[j] = Ks[(tx * 4 + j) * QPAD + k];
            #pragma unroll
            for (int i = 0; i < 4; i++)
                #pragma unroll
                for (int j = 0; j < 4; j++)
                    sacc[i][j] = fmaf(a[i], bq[j], sacc[i][j]);
        }
        #pragma unroll
        for (int i = 0; i < 4; i++)
            #pragma unroll
            for (int j = 0; j < 4; j++)
                Ss[(ty * 4 + i) * QPAD + tx * 4 + j] = sacc[i][j] * scale;
        __syncthreads();

        // Online softmax row update (one thread per row)
        if (tid < 64) {
            const int r = tid;
            float m = mrow[r];
            float mx = m;
            #pragma unroll 8
            for (int c = 0; c < 64; c++) mx = fmaxf(mx, Ss[r * QPAD + c]);
            float alpha = __expf(m - mx);
            float l = lrow[r] * alpha;
            #pragma unroll 8
            for (int c = 0; c < 64; c++) {
                float e = __expf(Ss[r * QPAD + c] - mx);
                Ss[r * QPAD + c] = e;
                l += e;
            }
            arow[r] = alpha;
            mrow[r] = mx;
            lrow[r] = l;
        }
        __syncthreads();

        // O = O*alpha + P V
        #pragma unroll
        for (int i = 0; i < 4; i++) {
            float al = arow[ty * 4 + i];
            #pragma unroll
            for (int j = 0; j < 4; j++) acc[i][j] *= al;
        }
        #pragma unroll 8
        for (int s = 0; s < 64; s++) {
            float p[4], vb[4];
            #pragma unroll
            for (int i = 0; i < 4; i++) p[i] = Ss[(ty * 4 + i) * QPAD + s];
            #pragma unroll
            for (int j = 0; j < 4; j++) vb[j] = Vs[s * 64 + tx * 4 + j];
            #pragma unroll
            for (int i = 0; i < 4; i++)
                #pragma unroll
                for (int j = 0; j < 4; j++)
                    acc[i][j] = fmaf(p[i], vb[j], acc[i][j]);
        }
        __syncthreads();
    }

    // Epilogue: divide by l, write y (B,T,H,D)
    #pragma unroll
    for (int i = 0; i < 4; i++) {
        float inv = 1.0f / lrow[ty * 4 + i];
        #pragma unroll
        for (int j = 0; j < 4; j++) {
            y[base + (size_t)(q0 + ty * 4 + i) * CC + tx * 4 + j] = acc[i][j] * inv;
        }
    }
}

// ---------------------------------------------------------------------------
// Launch
// ---------------------------------------------------------------------------
extern "C" void kernel_launch(void* const* d_in, const int* in_sizes, int n_in,
                              void* d_out, int out_size)
{
    const float* x   = (const float*)d_in[0];
    const float* cs  = (const float*)d_in[1];
    const float* sn  = (const float*)d_in[2];
    const float* Wq  = (const float*)d_in[3];
    const float* Wk  = (const float*)d_in[4];
    const float* Wv  = (const float*)d_in[5];
    const float* Wo  = (const float*)d_in[6];
    float* out = (float*)d_out;

    float *qb, *kb, *vb, *yb;
    cudaGetSymbolAddress((void**)&qb, g_q);
    cudaGetSymbolAddress((void**)&kb, g_k);
    cudaGetSymbolAddress((void**)&vb, g_v);
    cudaGetSymbolAddress((void**)&yb, g_y);

    const int M = BB * TT;   // 8192
    const int N = CC;        // 1024
    const int K = CC;        // 1024
    dim3 ggrid(N / BN, M / BM);   // (16, 128)

    gemm_nt<<<ggrid, 256>>>(x, Wq, qb, M, N, K);
    gemm_nt<<<ggrid, 256>>>(x, Wk, kb, M, N, K);
    gemm_nt<<<ggrid, 256>>>(x, Wv, vb, M, N, K);

    dim3 rgrid(BB * TT * HH, 2);
    rope_rms<<<rgrid, 32>>>(qb, kb, cs, sn);

    const int smem = (3 * 64 * QPAD + 64 * 64 + 3 * 64) * sizeof(float); // ~67 KB
    cudaFuncSetAttribute(flash_attn, cudaFuncAttributeMaxDynamicSharedMemorySize, smem);
    dim3 fgrid(TT / 64, BB * HH);   // (32, 64)
    flash_attn<<<fgrid, 256, smem>>>(qb, kb, vb, yb);

    gemm_nt<<<ggrid, 256>>>(yb, Wo, out, M, N, K);
}

// round 2
// speedup vs baseline: 2.5685x; 2.5685x over previous
#include <cuda_runtime.h>
#include <cuda_bf16.h>
#include <math.h>
#include <stdint.h>

#define BB 4
#define TT 2048
#define CC 1024
#define HH 16
#define DD 64
#define EPS 1.1920929e-07f

// ---------------------------------------------------------------------------
// Scratch (allocation-free rule)
// ---------------------------------------------------------------------------
__device__ float g_q[BB * TT * CC];
__device__ float g_k[BB * TT * CC];
__device__ float g_v[BB * TT * CC];
__device__ float g_y[BB * TT * CC];

// ---------------------------------------------------------------------------
// tf32 helpers
// ---------------------------------------------------------------------------
__device__ __forceinline__ float to_tf32(float x) {
    uint32_t u;
    asm("cvt.rna.tf32.f32 %0, %1;" : "=r"(u) : "f"(x));
    return __uint_as_float(u);
}

__device__ __forceinline__ void mma_tf32(float* c, const uint32_t* a, const uint32_t* b) {
    asm volatile(
        "mma.sync.aligned.m16n8k8.row.col.f32.tf32.tf32.f32 "
        "{%0,%1,%2,%3}, {%4,%5,%6,%7}, {%8,%9}, {%0,%1,%2,%3};"
        : "+f"(c[0]), "+f"(c[1]), "+f"(c[2]), "+f"(c[3])
        : "r"(a[0]), "r"(a[1]), "r"(a[2]), "r"(a[3]), "r"(b[0]), "r"(b[1]));
}

// ---------------------------------------------------------------------------
// GEMM NT (tf32 MMA): C[m,n] = sum_k A[m,k] * W[n,k]
// Tile 128x64x32, 256 threads (8 warps, 4x2), warp tile 32x32.
// ---------------------------------------------------------------------------
#define GBM 128
#define GBN 64
#define GBK 32
#define GLDA 36   // GBK + 4 pad -> conflict-free fragment loads

__global__ __launch_bounds__(256) void gemm_nt_tf32(
    const float* __restrict__ A, const float* __restrict__ W,
    float* __restrict__ Cout, int M, int N, int K)
{
    __shared__ float As[GBM][GLDA];
    __shared__ float Ws[GBN][GLDA];

    const int tid = threadIdx.x;
    const int wid = tid >> 5;
    const int lane = tid & 31;
    const int wm = wid >> 1;       // 0..3
    const int wn = wid & 1;        // 0..1
    const int g = lane >> 2;       // group id (row of fragment)
    const int tg = lane & 3;       // thread in group

    const int m0 = blockIdx.y * GBM;
    const int n0 = blockIdx.x * GBN;

    float acc[2][4][4] = {};

    for (int k0 = 0; k0 < K; k0 += GBK) {
        // Stage A (128x32) and W (64x32), tf32-rounded
        #pragma unroll
        for (int t = 0; t < 4; t++) {
            int idx = tid + t * 256;
            int r = idx >> 3, c4 = (idx & 7) << 2;
            float4 v = *(const float4*)&A[(size_t)(m0 + r) * K + k0 + c4];
            As[r][c4 + 0] = to_tf32(v.x); As[r][c4 + 1] = to_tf32(v.y);
            As[r][c4 + 2] = to_tf32(v.z); As[r][c4 + 3] = to_tf32(v.w);
        }
        #pragma unroll
        for (int t = 0; t < 2; t++) {
            int idx = tid + t * 256;
            int r = idx >> 3, c4 = (idx & 7) << 2;
            float4 v = *(const float4*)&W[(size_t)(n0 + r) * K + k0 + c4];
            Ws[r][c4 + 0] = to_tf32(v.x); Ws[r][c4 + 1] = to_tf32(v.y);
            Ws[r][c4 + 2] = to_tf32(v.z); Ws[r][c4 + 3] = to_tf32(v.w);
        }
        __syncthreads();

        #pragma unroll
        for (int kk = 0; kk < GBK; kk += 8) {
            uint32_t af[2][4], bf[4][2];
            #pragma unroll
            for (int mi = 0; mi < 2; mi++) {
                int mb = wm * 32 + mi * 16;
                af[mi][0] = __float_as_uint(As[mb + g][kk + tg]);
                af[mi][1] = __float_as_uint(As[mb + g + 8][kk + tg]);
                af[mi][2] = __float_as_uint(As[mb + g][kk + tg + 4]);
                af[mi][3] = __float_as_uint(As[mb + g + 8][kk + tg + 4]);
            }
            #pragma unroll
            for (int ni = 0; ni < 4; ni++) {
                int nb = wn * 32 + ni * 8;
                bf[ni][0] = __float_as_uint(Ws[nb + g][kk + tg]);
                bf[ni][1] = __float_as_uint(Ws[nb + g][kk + tg + 4]);
            }
            #pragma unroll
            for (int mi = 0; mi < 2; mi++)
                #pragma unroll
                for (int ni = 0; ni < 4; ni++)
                    mma_tf32(acc[mi][ni], af[mi], bf[ni]);
        }
        __syncthreads();
    }

    #pragma unroll
    for (int mi = 0; mi < 2; mi++) {
        int r = m0 + wm * 32 + mi * 16 + g;
        #pragma unroll
        for (int ni = 0; ni < 4; ni++) {
            int c = n0 + wn * 32 + ni * 8 + tg * 2;
            *(float2*)&Cout[(size_t)r * N + c] =
                make_float2(acc[mi][ni][0], acc[mi][ni][1]);
            *(float2*)&Cout[(size_t)(r + 8) * N + c] =
                make_float2(acc[mi][ni][2], acc[mi][ni][3]);
        }
    }
}

// ---------------------------------------------------------------------------
// RoPE (concat-half) + RMSnorm, in-place on q,k. 8 rows per 256-thread block.
// ---------------------------------------------------------------------------
__global__ __launch_bounds__(256) void rope_rms(
    float* __restrict__ q, float* __restrict__ k,
    const float* __restrict__ cs, const float* __restrict__ sn)
{
    const int row = blockIdx.x * 8 + (threadIdx.x >> 5);
    const int i = threadIdx.x & 31;
    const int t = (row / HH) % TT;
    float* p = (blockIdx.y == 0 ? q : k) + (size_t)row * DD;

    float x1 = p[i];
    float x2 = p[i + 32];
    float c = cs[t * 32 + i];
    float s = sn[t * 32 + i];
    float y1 = x1 * c + x2 * s;
    float y2 = -x1 * s + x2 * c;

    float ss = y1 * y1 + y2 * y2;
    #pragma unroll
    for (int o = 16; o; o >>= 1) ss += __shfl_xor_sync(0xffffffffu, ss, o);
    float r = rsqrtf(ss * (1.0f / 64.0f) + EPS);

    p[i]      = y1 * r;
    p[i + 32] = y2 * r;
}

// ---------------------------------------------------------------------------
// Flash attention with tf32 MMA. Br=Bc=64, D=64. 128 threads (4 warps),
// each warp owns 16 query rows. Online softmax in registers (quad-resident).
// ---------------------------------------------------------------------------
#define FLD 68   // Qs/Ks/Ps row stride (64 + 4): conflict-free fragments
#define VLD 65   // Vt row stride: cheap transpose stores, ~2-way on loads

__global__ __launch_bounds__(128) void flash_tf32(
    const float* __restrict__ q, const float* __restrict__ kk,
    const float* __restrict__ vv, float* __restrict__ y)
{
    extern __shared__ float sm[];
    float (*Qs)[FLD] = (float(*)[FLD])sm;
    float (*Ks)[FLD] = (float(*)[FLD])(sm + 64 * FLD);
    float (*Ps)[FLD] = (float(*)[FLD])(sm + 2 * 64 * FLD);
    float (*Vt)[VLD] = (float(*)[VLD])(sm + 3 * 64 * FLD);

    const int tid = threadIdx.x;
    const int wid = tid >> 5;
    const int lane = tid & 31;
    const int g = lane >> 2, tg = lane & 3;

    const int bh = blockIdx.y;
    const size_t base = (size_t)(bh / HH) * TT * CC + (size_t)(bh % HH) * DD;
    const int q0 = blockIdx.x * 64;

    // Load Q tile, fold in 1/sqrt(D) and tf32-round
    #pragma unroll
    for (int t = 0; t < 8; t++) {
        int idx = tid + t * 128;
        int r = idx >> 4, c4 = (idx & 15) << 2;
        float4 v = *(const float4*)&q[base + (size_t)(q0 + r) * CC + c4];
        Qs[r][c4 + 0] = to_tf32(v.x * 0.125f);
        Qs[r][c4 + 1] = to_tf32(v.y * 0.125f);
        Qs[r][c4 + 2] = to_tf32(v.z * 0.125f);
        Qs[r][c4 + 3] = to_tf32(v.w * 0.125f);
    }

    float mrow[2] = {-1e30f, -1e30f};
    float lrow[2] = {0.0f, 0.0f};
    float oacc[8][4] = {};
    const int mb = wid * 16;

    for (int j0 = 0; j0 < TT; j0 += 64) {
        __syncthreads();   // previous PV done reading Ks/Vt
        // Load K (row-major) and V (transposed), tf32-rounded
        #pragma unroll
        for (int t = 0; t < 8; t++) {
            int idx = tid + t * 128;
            int r = idx >> 4, c4 = (idx & 15) << 2;
            size_t ga = base + (size_t)(j0 + r) * CC + c4;
            float4 kv = *(const float4*)&kk[ga];
            Ks[r][c4 + 0] = to_tf32(kv.x); Ks[r][c4 + 1] = to_tf32(kv.y);
            Ks[r][c4 + 2] = to_tf32(kv.z); Ks[r][c4 + 3] = to_tf32(kv.w);
            float4 vb = *(const float4*)&vv[ga];
            Vt[c4 + 0][r] = to_tf32(vb.x);
            Vt[c4 + 1][r] = to_tf32(vb.y);
            Vt[c4 + 2][r] = to_tf32(vb.z);
            Vt[c4 + 3][r] = to_tf32(vb.w);
        }
        __syncthreads();

        // S = (Q*scale) K^T
        float sacc[8][4] = {};
        #pragma unroll
        for (int ks = 0; ks < 64; ks += 8) {
            uint32_t af[4];
            af[0] = __float_as_uint(Qs[mb + g][ks + tg]);
            af[1] = __float_as_uint(Qs[mb + g + 8][ks + tg]);
            af[2] = __float_as_uint(Qs[mb + g][ks + tg + 4]);
            af[3] = __float_as_uint(Qs[mb + g + 8][ks + tg + 4]);
            #pragma unroll
            for (int ni = 0; ni < 8; ni++) {
                uint32_t bf[2];
                bf[0] = __float_as_uint(Ks[ni * 8 + g][ks + tg]);
                bf[1] = __float_as_uint(Ks[ni * 8 + g][ks + tg + 4]);
                mma_tf32(sacc[ni], af, bf);
            }
        }

        // Online softmax (rows g, g+8 of this warp's 16-row tile)
        float rmax[2] = {-1e30f, -1e30f};
        #pragma unroll
        for (int ni = 0; ni < 8; ni++) {
            rmax[0] = fmaxf(rmax[0], fmaxf(sacc[ni][0], sacc[ni][1]));
            rmax[1] = fmaxf(rmax[1], fmaxf(sacc[ni][2], sacc[ni][3]));
        }
        #pragma unroll
        for (int o = 1; o <= 2; o <<= 1) {
            rmax[0] = fmaxf(rmax[0], __shfl_xor_sync(0xffffffffu, rmax[0], o));
            rmax[1] = fmaxf(rmax[1], __shfl_xor_sync(0xffffffffu, rmax[1], o));
        }
        float nm0 = fmaxf(mrow[0], rmax[0]);
        float nm1 = fmaxf(mrow[1], rmax[1]);
        float alpha0 = __expf(mrow[0] - nm0);
        float alpha1 = __expf(mrow[1] - nm1);

        float rsum[2] = {0.0f, 0.0f};
        #pragma unroll
        for (int ni = 0; ni < 8; ni++) {
            float p0 = __expf(sacc[ni][0] - nm0);
            float p1 = __expf(sacc[ni][1] - nm0);
            float p2 = __expf(sacc[ni][2] - nm1);
            float p3 = __expf(sacc[ni][3] - nm1);
            rsum[0] += p0 + p1;
            rsum[1] += p2 + p3;
            int c = ni * 8 + tg * 2;
            Ps[mb + g][c]         = to_tf32(p0);
            Ps[mb + g][c + 1]     = to_tf32(p1);
            Ps[mb + g + 8][c]     = to_tf32(p2);
            Ps[mb + g + 8][c + 1] = to_tf32(p3);
        }
        #pragma unroll
        for (int o = 1; o <= 2; o <<= 1) {
            rsum[0] += __shfl_xor_sync(0xffffffffu, rsum[0], o);
            rsum[1] += __shfl_xor_sync(0xffffffffu, rsum[1], o);
        }
        lrow[0] = lrow[0] * alpha0 + rsum[0];
        lrow[1] = lrow[1] * alpha1 + rsum[1];
        mrow[0] = nm0;
        mrow[1] = nm1;

        #pragma unroll
        for (int ni = 0; ni < 8; ni++) {
            oacc[ni][0] *= alpha0; oacc[ni][1] *= alpha0;
            oacc[ni][2] *= alpha1; oacc[ni][3] *= alpha1;
        }
        __syncwarp();   // Ps is warp-local (own 16 rows)

        // O += P V
        #pragma unroll
        for (int ks = 0; ks < 64; ks += 8) {
            uint32_t af[4];
            af[0] = __float_as_uint(Ps[mb + g][ks + tg]);
            af[1] = __float_as_uint(Ps[mb + g + 8][ks + tg]);
            af[2] = __float_as_uint(Ps[mb + g][ks + tg + 4]);
            af[3] = __float_as_uint(Ps[mb + g + 8][ks + tg + 4]);
            #pragma unroll
            for (int ni = 0; ni < 8; ni++) {
                uint32_t bf[2];
                bf[0] = __float_as_uint(Vt[ni * 8 + g][ks + tg]);
                bf[1] = __float_as_uint(Vt[ni * 8 + g][ks + tg + 4]);
                mma_tf32(oacc[ni], af, bf);
            }
        }
    }

    // Epilogue: normalize by l, write (B,T,H,D)
    float inv0 = 1.0f / lrow[0];
    float inv1 = 1.0f / lrow[1];
    int r0 = q0 + mb + g;
    #pragma unroll
    for (int ni = 0; ni < 8; ni++) {
        int c = ni * 8 + tg * 2;
        *(float2*)&y[base + (size_t)r0 * CC + c] =
            make_float2(oacc[ni][0] * inv0, oacc[ni][1] * inv0);
        *(float2*)&y[base + (size_t)(r0 + 8) * CC + c] =
            make_float2(oacc[ni][2] * inv1, oacc[ni][3] * inv1);
    }
}

// ---------------------------------------------------------------------------
// Launch
// ---------------------------------------------------------------------------
extern "C" void kernel_launch(void* const* d_in, const int* in_sizes, int n_in,
                              void* d_out, int out_size)
{
    const float* x  = (const float*)d_in[0];
    const float* cs = (const float*)d_in[1];
    const float* sn = (const float*)d_in[2];
    const float* Wq = (const float*)d_in[3];
    const float* Wk = (const float*)d_in[4];
    const float* Wv = (const float*)d_in[5];
    const float* Wo = (const float*)d_in[6];
    float* out = (float*)d_out;

    float *qb, *kb, *vb, *yb;
    cudaGetSymbolAddress((void**)&qb, g_q);
    cudaGetSymbolAddress((void**)&kb, g_k);
    cudaGetSymbolAddress((void**)&vb, g_v);
    cudaGetSymbolAddress((void**)&yb, g_y);

    const int M = BB * TT, N = CC, K = CC;
    dim3 ggrid(N / GBN, M / GBM);   // (16, 64)

    gemm_nt_tf32<<<ggrid, 256>>>(x, Wq, qb, M, N, K);
    gemm_nt_tf32<<<ggrid, 256>>>(x, Wk, kb, M, N, K);
    gemm_nt_tf32<<<ggrid, 256>>>(x, Wv, vb, M, N, K);

    dim3 rgrid(BB * TT * HH / 8, 2);
    rope_rms<<<rgrid, 256>>>(qb, kb, cs, sn);

    const int smem = (3 * 64 * FLD + 64 * VLD) * sizeof(float);  // ~68.9 KB
    cudaFuncSetAttribute(flash_tf32, cudaFuncAttributeMaxDynamicSharedMemorySize, smem);
    dim3 fgrid(TT / 64, BB * HH);   // (32, 64)
    flash_tf32<<<fgrid, 128, smem>>>(qb, kb, vb, yb);

    gemm_nt_tf32<<<ggrid, 256>>>(yb, Wo, out, M, N, K);
}

// round 3
// speedup vs baseline: 2.7369x; 1.0656x over previous
#include <cuda_runtime.h>
#include <cuda_bf16.h>
#include <math.h>
#include <stdint.h>

#define BB 4
#define TT 2048
#define CC 1024
#define HH 16
#define DD 64
#define EPS 1.1920929e-07f

// ---------------------------------------------------------------------------
// Scratch (allocation-free rule)
// ---------------------------------------------------------------------------
__device__ float g_q[BB * TT * CC];
__device__ float g_k[BB * TT * CC];
__device__ float g_v[BB * TT * CC];
__device__ float g_y[BB * TT * CC];

// ---------------------------------------------------------------------------
// tf32 helpers
// ---------------------------------------------------------------------------
__device__ __forceinline__ float to_tf32(float x) {
    uint32_t u;
    asm("cvt.rna.tf32.f32 %0, %1;" : "=r"(u) : "f"(x));
    return __uint_as_float(u);
}

__device__ __forceinline__ void mma_tf32(float* c, const uint32_t* a, const uint32_t* b) {
    asm volatile(
        "mma.sync.aligned.m16n8k8.row.col.f32.tf32.tf32.f32 "
        "{%0,%1,%2,%3}, {%4,%5,%6,%7}, {%8,%9}, {%0,%1,%2,%3};"
        : "+f"(c[0]), "+f"(c[1]), "+f"(c[2]), "+f"(c[3])
        : "r"(a[0]), "r"(a[1]), "r"(a[2]), "r"(a[3]), "r"(b[0]), "r"(b[1]));
}

// ---------------------------------------------------------------------------
// GEMM NT (tf32 MMA): C[m,n] = sum_k A[m,k] * W[n,k]
// 128x128x16 tile, 256 threads (8 warps as 2x4), warp tile 64x32.
// Double-buffered smem + register prefetch of next tile.
// blockIdx.z selects among up to 3 (W, C) pairs (fused QKV).
// ---------------------------------------------------------------------------
#define GBM 128
#define GBN 128
#define GBK 16
#define GPAD 20   // row stride: conflict-free fragment loads

__global__ __launch_bounds__(256) void gemm3_tf32(
    const float* __restrict__ A,
    const float* __restrict__ W0, const float* __restrict__ W1, const float* __restrict__ W2,
    float* __restrict__ C0, float* __restrict__ C1, float* __restrict__ C2,
    int M, int N, int K)
{
    __shared__ float As[2][GBM][GPAD];
    __shared__ float Ws[2][GBN][GPAD];

    const float* W = blockIdx.z == 0 ? W0 : (blockIdx.z == 1 ? W1 : W2);
    float* Cout    = blockIdx.z == 0 ? C0 : (blockIdx.z == 1 ? C1 : C2);

    const int tid = threadIdx.x;
    const int wid = tid >> 5;
    const int lane = tid & 31;
    const int wm = wid & 1;        // 0..1  (64-row slab)
    const int wn = wid >> 1;       // 0..3  (32-col slab)
    const int g = lane >> 2;       // 0..7
    const int tg = lane & 3;       // 0..3

    const int m0 = blockIdx.y * GBM;
    const int n0 = blockIdx.x * GBN;

    // staging indices: each thread loads 2 float4 for A and 2 for W per tile
    const int lr = tid >> 2;          // 0..63
    const int lc = (tid & 3) << 2;    // 0,4,8,12

    const float* Arow0 = &A[(size_t)(m0 + lr) * K + lc];
    const float* Arow1 = &A[(size_t)(m0 + lr + 64) * K + lc];
    const float* Wrow0 = &W[(size_t)(n0 + lr) * K + lc];
    const float* Wrow1 = &W[(size_t)(n0 + lr + 64) * K + lc];

    float acc[4][4][4] = {};

    // preload tile 0
    {
        float4 a0 = *(const float4*)Arow0;
        float4 a1 = *(const float4*)Arow1;
        float4 w0 = *(const float4*)Wrow0;
        float4 w1 = *(const float4*)Wrow1;
        As[0][lr     ][lc+0]=to_tf32(a0.x); As[0][lr     ][lc+1]=to_tf32(a0.y);
        As[0][lr     ][lc+2]=to_tf32(a0.z); As[0][lr     ][lc+3]=to_tf32(a0.w);
        As[0][lr + 64][lc+0]=to_tf32(a1.x); As[0][lr + 64][lc+1]=to_tf32(a1.y);
        As[0][lr + 64][lc+2]=to_tf32(a1.z); As[0][lr + 64][lc+3]=to_tf32(a1.w);
        Ws[0][lr     ][lc+0]=to_tf32(w0.x); Ws[0][lr     ][lc+1]=to_tf32(w0.y);
        Ws[0][lr     ][lc+2]=to_tf32(w0.z); Ws[0][lr     ][lc+3]=to_tf32(w0.w);
        Ws[0][lr + 64][lc+0]=to_tf32(w1.x); Ws[0][lr + 64][lc+1]=to_tf32(w1.y);
        Ws[0][lr + 64][lc+2]=to_tf32(w1.z); Ws[0][lr + 64][lc+3]=to_tf32(w1.w);
    }
    __syncthreads();

    const int nt = K / GBK;
    for (int kt = 0; kt < nt; kt++) {
        const int cur = kt & 1;
        const bool has = (kt + 1) < nt;
        float4 a0, a1, w0, w1;
        if (has) {
            const int k1 = (kt + 1) * GBK;
            a0 = *(const float4*)(Arow0 + k1);
            a1 = *(const float4*)(Arow1 + k1);
            w0 = *(const float4*)(Wrow0 + k1);
            w1 = *(const float4*)(Wrow1 + k1);
        }

        #pragma unroll
        for (int kk = 0; kk < GBK; kk += 8) {
            uint32_t af[4][4], bf[4][2];
            #pragma unroll
            for (int mi = 0; mi < 4; mi++) {
                int mb = wm * 64 + mi * 16;
                af[mi][0] = __float_as_uint(As[cur][mb + g    ][kk + tg]);
                af[mi][1] = __float_as_uint(As[cur][mb + g + 8][kk + tg]);
                af[mi][2] = __float_as_uint(As[cur][mb + g    ][kk + tg + 4]);
                af[mi][3] = __float_as_uint(As[cur][mb + g + 8][kk + tg + 4]);
            }
            #pragma unroll
            for (int ni = 0; ni < 4; ni++) {
                int nb = wn * 32 + ni * 8;
                bf[ni][0] = __float_as_uint(Ws[cur][nb + g][kk + tg]);
                bf[ni][1] = __float_as_uint(Ws[cur][nb + g][kk + tg + 4]);
            }
            #pragma unroll
            for (int mi = 0; mi < 4; mi++)
                #pragma unroll
                for (int ni = 0; ni < 4; ni++)
                    mma_tf32(acc[mi][ni], af[mi], bf[ni]);
        }

        if (has) {
            const int nb = cur ^ 1;
            As[nb][lr     ][lc+0]=to_tf32(a0.x); As[nb][lr     ][lc+1]=to_tf32(a0.y);
            As[nb][lr     ][lc+2]=to_tf32(a0.z); As[nb][lr     ][lc+3]=to_tf32(a0.w);
            As[nb][lr + 64][lc+0]=to_tf32(a1.x); As[nb][lr + 64][lc+1]=to_tf32(a1.y);
            As[nb][lr + 64][lc+2]=to_tf32(a1.z); As[nb][lr + 64][lc+3]=to_tf32(a1.w);
            Ws[nb][lr     ][lc+0]=to_tf32(w0.x); Ws[nb][lr     ][lc+1]=to_tf32(w0.y);
            Ws[nb][lr     ][lc+2]=to_tf32(w0.z); Ws[nb][lr     ][lc+3]=to_tf32(w0.w);
            Ws[nb][lr + 64][lc+0]=to_tf32(w1.x); Ws[nb][lr + 64][lc+1]=to_tf32(w1.y);
            Ws[nb][lr + 64][lc+2]=to_tf32(w1.z); Ws[nb][lr + 64][lc+3]=to_tf32(w1.w);
        }
        __syncthreads();
    }

    #pragma unroll
    for (int mi = 0; mi < 4; mi++) {
        int r = m0 + wm * 64 + mi * 16 + g;
        #pragma unroll
        for (int ni = 0; ni < 4; ni++) {
            int c = n0 + wn * 32 + ni * 8 + tg * 2;
            *(float2*)&Cout[(size_t)r * N + c] =
                make_float2(acc[mi][ni][0], acc[mi][ni][1]);
            *(float2*)&Cout[(size_t)(r + 8) * N + c] =
                make_float2(acc[mi][ni][2], acc[mi][ni][3]);
        }
    }
}

// ---------------------------------------------------------------------------
// RoPE (concat-half) + RMSnorm, in-place on q,k. 8 rows per 256-thread block.
// ---------------------------------------------------------------------------
__global__ __launch_bounds__(256) void rope_rms(
    float* __restrict__ q, float* __restrict__ k,
    const float* __restrict__ cs, const float* __restrict__ sn)
{
    const int row = blockIdx.x * 8 + (threadIdx.x >> 5);
    const int i = threadIdx.x & 31;
    const int t = (row / HH) % TT;
    float* p = (blockIdx.y == 0 ? q : k) + (size_t)row * DD;

    float x1 = p[i];
    float x2 = p[i + 32];
    float c = cs[t * 32 + i];
    float s = sn[t * 32 + i];
    float y1 = x1 * c + x2 * s;
    float y2 = -x1 * s + x2 * c;

    float ss = y1 * y1 + y2 * y2;
    #pragma unroll
    for (int o = 16; o; o >>= 1) ss += __shfl_xor_sync(0xffffffffu, ss, o);
    float r = rsqrtf(ss * (1.0f / 64.0f) + EPS);

    p[i]      = y1 * r;
    p[i + 32] = y2 * r;
}

// ---------------------------------------------------------------------------
// Flash attention, tf32 MMA. Br=128, Bc=64, D=64. 256 threads (8 warps),
// each warp owns 16 query rows. Online softmax in registers.
// ---------------------------------------------------------------------------
#define FLD 68   // Qs/Ks/Ps row stride (64 + 4)
#define VLD 65   // Vt row stride

__global__ __launch_bounds__(256) void flash_tf32(
    const float* __restrict__ q, const float* __restrict__ kk,
    const float* __restrict__ vv, float* __restrict__ y)
{
    extern __shared__ float sm[];
    float (*Qs)[FLD] = (float(*)[FLD])sm;                       // 128 x 68
    float (*Ks)[FLD] = (float(*)[FLD])(sm + 128 * FLD);         // 64 x 68
    float (*Ps)[FLD] = (float(*)[FLD])(sm + 192 * FLD);         // 128 x 68
    float (*Vt)[VLD] = (float(*)[VLD])(sm + 320 * FLD);         // 64 x 65

    const int tid = threadIdx.x;
    const int wid = tid >> 5;
    const int lane = tid & 31;
    const int g = lane >> 2, tg = lane & 3;

    const int bh = blockIdx.y;
    const size_t base = (size_t)(bh / HH) * TT * CC + (size_t)(bh % HH) * DD;
    const int q0 = blockIdx.x * 128;

    // Load Q tile (128 x 64), fold 1/sqrt(D), tf32-round
    #pragma unroll
    for (int t = 0; t < 8; t++) {
        int idx = tid + t * 256;
        int r = idx >> 4, c4 = (idx & 15) << 2;
        float4 v = *(const float4*)&q[base + (size_t)(q0 + r) * CC + c4];
        Qs[r][c4 + 0] = to_tf32(v.x * 0.125f);
        Qs[r][c4 + 1] = to_tf32(v.y * 0.125f);
        Qs[r][c4 + 2] = to_tf32(v.z * 0.125f);
        Qs[r][c4 + 3] = to_tf32(v.w * 0.125f);
    }

    float mrow[2] = {-1e30f, -1e30f};
    float lrow[2] = {0.0f, 0.0f};
    float oacc[8][4] = {};
    const int mb = wid * 16;

    for (int j0 = 0; j0 < TT; j0 += 64) {
        __syncthreads();   // previous PV done reading Ks/Vt
        // Load K (row-major) and V (transposed), tf32-rounded
        #pragma unroll
        for (int t = 0; t < 4; t++) {
            int idx = tid + t * 256;
            int r = idx >> 4, c4 = (idx & 15) << 2;
            size_t ga = base + (size_t)(j0 + r) * CC + c4;
            float4 kv = *(const float4*)&kk[ga];
            Ks[r][c4 + 0] = to_tf32(kv.x); Ks[r][c4 + 1] = to_tf32(kv.y);
            Ks[r][c4 + 2] = to_tf32(kv.z); Ks[r][c4 + 3] = to_tf32(kv.w);
            float4 vb = *(const float4*)&vv[ga];
            Vt[c4 + 0][r] = to_tf32(vb.x);
            Vt[c4 + 1][r] = to_tf32(vb.y);
            Vt[c4 + 2][r] = to_tf32(vb.z);
            Vt[c4 + 3][r] = to_tf32(vb.w);
        }
        __syncthreads();

        // S = (Q*scale) K^T
        float sacc[8][4] = {};
        #pragma unroll
        for (int ks = 0; ks < 64; ks += 8) {
            uint32_t af[4];
            af[0] = __float_as_uint(Qs[mb + g    ][ks + tg]);
            af[1] = __float_as_uint(Qs[mb + g + 8][ks + tg]);
            af[2] = __float_as_uint(Qs[mb + g    ][ks + tg + 4]);
            af[3] = __float_as_uint(Qs[mb + g + 8][ks + tg + 4]);
            #pragma unroll
            for (int ni = 0; ni < 8; ni++) {
                uint32_t bf[2];
                bf[0] = __float_as_uint(Ks[ni * 8 + g][ks + tg]);
                bf[1] = __float_as_uint(Ks[ni * 8 + g][ks + tg + 4]);
                mma_tf32(sacc[ni], af, bf);
            }
        }

        // Online softmax (rows g, g+8 of this warp's 16-row tile)
        float rmax[2] = {-1e30f, -1e30f};
        #pragma unroll
        for (int ni = 0; ni < 8; ni++) {
            rmax[0] = fmaxf(rmax[0], fmaxf(sacc[ni][0], sacc[ni][1]));
            rmax[1] = fmaxf(rmax[1], fmaxf(sacc[ni][2], sacc[ni][3]));
        }
        #pragma unroll
        for (int o = 1; o <= 2; o <<= 1) {
            rmax[0] = fmaxf(rmax[0], __shfl_xor_sync(0xffffffffu, rmax[0], o));
            rmax[1] = fmaxf(rmax[1], __shfl_xor_sync(0xffffffffu, rmax[1], o));
        }
        float nm0 = fmaxf(mrow[0], rmax[0]);
        float nm1 = fmaxf(mrow[1], rmax[1]);
        float alpha0 = __expf(mrow[0] - nm0);
        float alpha1 = __expf(mrow[1] - nm1);

        float rsum[2] = {0.0f, 0.0f};
        #pragma unroll
        for (int ni = 0; ni < 8; ni++) {
            float p0 = __expf(sacc[ni][0] - nm0);
            float p1 = __expf(sacc[ni][1] - nm0);
            float p2 = __expf(sacc[ni][2] - nm1);
            float p3 = __expf(sacc[ni][3] - nm1);
            rsum[0] += p0 + p1;
            rsum[1] += p2 + p3;
            int c = ni * 8 + tg * 2;
            Ps[mb + g    ][c]     = to_tf32(p0);
            Ps[mb + g    ][c + 1] = to_tf32(p1);
            Ps[mb + g + 8][c]     = to_tf32(p2);
            Ps[mb + g + 8][c + 1] = to_tf32(p3);
        }
        #pragma unroll
        for (int o = 1; o <= 2; o <<= 1) {
            rsum[0] += __shfl_xor_sync(0xffffffffu, rsum[0], o);
            rsum[1] += __shfl_xor_sync(0xffffffffu, rsum[1], o);
        }
        lrow[0] = lrow[0] * alpha0 + rsum[0];
        lrow[1] = lrow[1] * alpha1 + rsum[1];
        mrow[0] = nm0;
        mrow[1] = nm1;

        #pragma unroll
        for (int ni = 0; ni < 8; ni++) {
            oacc[ni][0] *= alpha0; oacc[ni][1] *= alpha0;
            oacc[ni][2] *= alpha1; oacc[ni][3] *= alpha1;
        }
        __syncwarp();   // Ps rows are warp-local

        // O += P V
        #pragma unroll
        for (int ks = 0; ks < 64; ks += 8) {
            uint32_t af[4];
            af[0] = __float_as_uint(Ps[mb + g    ][ks + tg]);
            af[1] = __float_as_uint(Ps[mb + g + 8][ks + tg]);
            af[2] = __float_as_uint(Ps[mb + g    ][ks + tg + 4]);
            af[3] = __float_as_uint(Ps[mb + g + 8][ks + tg + 4]);
            #pragma unroll
            for (int ni = 0; ni < 8; ni++) {
                uint32_t bf[2];
                bf[0] = __float_as_uint(Vt[ni * 8 + g][ks + tg]);
                bf[1] = __float_as_uint(Vt[ni * 8 + g][ks + tg + 4]);
                mma_tf32(oacc[ni], af, bf);
            }
        }
    }

    // Epilogue: normalize by l, write (B,T,H,D)
    float inv0 = 1.0f / lrow[0];
    float inv1 = 1.0f / lrow[1];
    int r0 = q0 + mb + g;
    #pragma unroll
    for (int ni = 0; ni < 8; ni++) {
        int c = ni * 8 + tg * 2;
        *(float2*)&y[base + (size_t)r0 * CC + c] =
            make_float2(oacc[ni][0] * inv0, oacc[ni][1] * inv0);
        *(float2*)&y[base + (size_t)(r0 + 8) * CC + c] =
            make_float2(oacc[ni][2] * inv1, oacc[ni][3] * inv1);
    }
}

// ---------------------------------------------------------------------------
// Launch
// ---------------------------------------------------------------------------
extern "C" void kernel_launch(void* const* d_in, const int* in_sizes, int n_in,
                              void* d_out, int out_size)
{
    const float* x  = (const float*)d_in[0];
    const float* cs = (const float*)d_in[1];
    const float* sn = (const float*)d_in[2];
    const float* Wq = (const float*)d_in[3];
    const float* Wk = (const float*)d_in[4];
    const float* Wv = (const float*)d_in[5];
    const float* Wo = (const float*)d_in[6];
    float* out = (float*)d_out;

    float *qb, *kb, *vb, *yb;
    cudaGetSymbolAddress((void**)&qb, g_q);
    cudaGetSymbolAddress((void**)&kb, g_k);
    cudaGetSymbolAddress((void**)&vb, g_v);
    cudaGetSymbolAddress((void**)&yb, g_y);

    const int M = BB * TT, N = CC, K = CC;

    // Fused QKV projections: grid.z selects weight/output
    dim3 qkvgrid(N / GBN, M / GBM, 3);   // (8, 64, 3)
    gemm3_tf32<<<qkvgrid, 256>>>(x, Wq, Wk, Wv, qb, kb, vb, M, N, K);

    dim3 rgrid(BB * TT * HH / 8, 2);
    rope_rms<<<rgrid, 256>>>(qb, kb, cs, sn);

    const int smem = (320 * FLD + 64 * VLD) * sizeof(float);  // ~101 KB
    cudaFuncSetAttribute(flash_tf32, cudaFuncAttributeMaxDynamicSharedMemorySize, smem);
    dim3 fgrid(TT / 128, BB * HH);   // (16, 64)
    flash_tf32<<<fgrid, 256, smem>>>(qb, kb, vb, yb);

    dim3 ogrid(N / GBN, M / GBM, 1);     // (8, 64, 1)
    gemm3_tf32<<<ogrid, 256>>>(yb, Wo, Wo, Wo, out, out, out, M, N, K);
}